// round 6
// baseline (speedup 1.0000x reference)
#include <cuda_runtime.h>

// Problem constants (fixed by the reference): B=8, N=2048, D=2
#define TB 8
#define TN 2048
#define ROWS 16
#define NBLK (TB * (TN / ROWS))   // 1024 blocks
#define THREADS 256

// Scratch (no allocation allowed in kernel_launch)
__device__ float g_q[TB * TN * 2];     // q = embedding + abs_coords, [B, N, 2]
__device__ float g_part[NBLK];         // per-block partial sums

// ---------------------------------------------------------------------------
// Kernel 0: fuse q = embedding + abs_coords  (64 K float2 adds, trivial)
// ---------------------------------------------------------------------------
__global__ void prep_kernel(const float* __restrict__ emb,
                            const float* __restrict__ crd) {
    int i = blockIdx.x * blockDim.x + threadIdx.x;
    if (i < TB * TN * 2) g_q[i] = emb[i] + crd[i];
}

// ---------------------------------------------------------------------------
// Kernel 1: masked pairwise sum.
// Block = (b, 16-row chunk). q[b] (16KB) staged in smem; mask streamed int4.
// Accumulates  count_masked  and  sum_masked(exp(-d2/10)); partial = cnt - esum.
// ---------------------------------------------------------------------------
__global__ __launch_bounds__(THREADS) void pair_kernel(const int* __restrict__ mask) {
    __shared__ float qs[TN * 2];           // q[b] as interleaved (x,y)
    __shared__ float w_es[THREADS / 32];
    __shared__ float w_cn[THREADS / 32];

    const int tid  = threadIdx.x;
    const int b    = blockIdx.x / (TN / ROWS);
    const int row0 = (blockIdx.x % (TN / ROWS)) * ROWS;

    // Stage q[b] -> smem with float4 loads (1024 float4, 4 per thread)
    const float4* gq4 = (const float4*)(g_q + (size_t)b * TN * 2);
    float4* qs4 = (float4*)qs;
#pragma unroll
    for (int k = 0; k < (TN * 2 / 4) / THREADS; ++k)
        qs4[tid + k * THREADS] = gq4[tid + k * THREADS];
    __syncthreads();

    const float K = -0.14426950408889634f;  // -log2(e)/10
    float esum = 0.f;
    int   cnt  = 0;

#pragma unroll 1
    for (int r = 0; r < ROWS; ++r) {
        const int i = row0 + r;
        const float qix = qs[2 * i];
        const float qiy = qs[2 * i + 1];
        const int4* mrow = (const int4*)(mask + ((size_t)b * TN + i) * TN);
#pragma unroll
        for (int it = 0; it < (TN / 4) / THREADS; ++it) {
            const int j4 = tid + it * THREADS;     // int4 index; j = 4*j4
            const int4  m  = __ldg(&mrow[j4]);     // 4 mask values
            const float4 qa = qs4[2 * j4];         // q[4j4], q[4j4+1]
            const float4 qb = qs4[2 * j4 + 1];     // q[4j4+2], q[4j4+3]

            const float px[4] = {qa.x, qa.z, qb.x, qb.z};
            const float py[4] = {qa.y, qa.w, qb.y, qb.w};
            const int   mm[4] = {m.x, m.y, m.z, m.w};
#pragma unroll
            for (int u = 0; u < 4; ++u) {
                const float dx = qix - px[u];
                const float dy = qiy - py[u];
                const float d2 = fmaf(dx, dx, dy * dy);
                float e;
                asm("ex2.approx.ftz.f32 %0, %1;" : "=f"(e) : "f"(d2 * K));
                if (mm[u]) { esum += e; cnt++; }   // mask values are 0/1
            }
        }
    }

    // Deterministic block reduction: warp shuffle -> smem -> thread 0
    float c = (float)cnt;
#pragma unroll
    for (int o = 16; o; o >>= 1) {
        esum += __shfl_down_sync(0xffffffffu, esum, o);
        c    += __shfl_down_sync(0xffffffffu, c, o);
    }
    if ((tid & 31) == 0) { w_es[tid >> 5] = esum; w_cn[tid >> 5] = c; }
    __syncthreads();
    if (tid == 0) {
        float es = 0.f, cc = 0.f;
#pragma unroll
        for (int k = 0; k < THREADS / 32; ++k) { es += w_es[k]; cc += w_cn[k]; }
        g_part[blockIdx.x] = cc - es;   // sum of (1 - exp(-d2/10)) over masked pairs
    }
}

// ---------------------------------------------------------------------------
// Kernel 2: deterministic final reduction of 1024 partials
// ---------------------------------------------------------------------------
__global__ void finalize_kernel(float* __restrict__ out) {
    __shared__ float s[256];
    const int tid = threadIdx.x;
    float v = 0.f;
#pragma unroll
    for (int k = tid; k < NBLK; k += 256) v += g_part[k];   // fixed order
    s[tid] = v;
    __syncthreads();
#pragma unroll
    for (int o = 128; o; o >>= 1) {
        if (tid < o) s[tid] += s[tid + o];
        __syncthreads();
    }
    if (tid == 0) out[0] = s[0];
}

// ---------------------------------------------------------------------------
extern "C" void kernel_launch(void* const* d_in, const int* in_sizes, int n_in,
                              void* d_out, int out_size) {
    const float* emb  = (const float*)d_in[0];   // embedding  [B,N,D] f32
    const float* crd  = (const float*)d_in[1];   // abs_coords [B,N,D] f32
    const int*   mask = (const int*)d_in[2];     // patch_mask [B,N,N] i32
    float* out = (float*)d_out;

    prep_kernel<<<(TB * TN * 2 + 255) / 256, 256>>>(emb, crd);
    pair_kernel<<<NBLK, THREADS>>>(mask);
    finalize_kernel<<<1, 256>>>(out);
}

// round 7
// speedup vs baseline: 1.3472x; 1.3472x over previous
#include <cuda_runtime.h>

// Problem constants (fixed by the reference): B=8, N=2048, D=2
#define TB 8
#define TN 2048
#define ROWS 16
#define NCHUNK (TN / ROWS)          // 128 row-chunks per batch
#define NBLK (TB * NCHUNK)          // 1024 blocks
#define THREADS 256
#define CIT ((TN / 4) / THREADS)    // 2 column iterations (int4 granularity)
#define RU 4                        // rows per load-batch group

// Scratch (no allocation allowed in kernel_launch)
__device__ float g_part[NBLK];
__device__ unsigned int g_done;     // zero-init; last block resets it each run

__global__ __launch_bounds__(THREADS) void pair_kernel(
    const float* __restrict__ emb, const float* __restrict__ crd,
    const int* __restrict__ mask, float* __restrict__ out) {
    __shared__ float qs[TN * 2];                 // q[b] interleaved (x,y)
    __shared__ float w_es[THREADS / 32];
    __shared__ float w_cn[THREADS / 32];
    __shared__ int   s_last;

    const int tid  = threadIdx.x;
    const int b    = blockIdx.x / NCHUNK;
    const int row0 = (blockIdx.x % NCHUNK) * ROWS;

    // ---- stage q[b] = emb[b] + crd[b] into smem (fused, no prep kernel) ----
    const float4* e4 = (const float4*)(emb + (size_t)b * TN * 2);
    const float4* c4 = (const float4*)(crd + (size_t)b * TN * 2);
    float4* qs4 = (float4*)qs;
#pragma unroll
    for (int k = 0; k < (TN * 2 / 4) / THREADS; ++k) {       // 4 iters
        const float4 e = e4[tid + k * THREADS];
        const float4 c = c4[tid + k * THREADS];
        float4 q;
        q.x = e.x + c.x; q.y = e.y + c.y; q.z = e.z + c.z; q.w = e.w + c.w;
        qs4[tid + k * THREADS] = q;
    }
    __syncthreads();

    // ---- hoist this thread's column q-values to registers (row-invariant) ----
    float px[CIT][4], py[CIT][4];
#pragma unroll
    for (int it = 0; it < CIT; ++it) {
        const int j4 = tid + it * THREADS;
        const float4 qa = qs4[2 * j4];
        const float4 qb = qs4[2 * j4 + 1];
        px[it][0] = qa.x; py[it][0] = qa.y;
        px[it][1] = qa.z; py[it][1] = qa.w;
        px[it][2] = qb.x; py[it][2] = qb.y;
        px[it][3] = qb.z; py[it][3] = qb.w;
    }

    const float K = -0.14426950408889634f;       // -log2(e)/10
    float esum = 0.f;
    int   cnt  = 0;

    const int4* mb = (const int4*)(mask + ((size_t)b * TN + row0) * TN);
    const int RSTRIDE = TN / 4;                  // int4 stride per mask row

#pragma unroll 1
    for (int r0 = 0; r0 < ROWS; r0 += RU) {
        // batch 8 independent int4 mask loads (MLP_p1 = 8)
        int4 m[RU][CIT];
#pragma unroll
        for (int ru = 0; ru < RU; ++ru)
#pragma unroll
            for (int it = 0; it < CIT; ++it)
                m[ru][it] = __ldcs(&mb[(size_t)(r0 + ru) * RSTRIDE + tid + it * THREADS]);

#pragma unroll
        for (int ru = 0; ru < RU; ++ru) {
            const int i = row0 + r0 + ru;
            const float qix = qs[2 * i];
            const float qiy = qs[2 * i + 1];
#pragma unroll
            for (int it = 0; it < CIT; ++it) {
                const int mm[4] = {m[ru][it].x, m[ru][it].y, m[ru][it].z, m[ru][it].w};
#pragma unroll
                for (int u = 0; u < 4; ++u) {
                    const float dx = qix - px[it][u];
                    const float dy = qiy - py[it][u];
                    const float d2 = fmaf(dx, dx, dy * dy);
                    float e;
                    asm("ex2.approx.ftz.f32 %0, %1;" : "=f"(e) : "f"(d2 * K));
                    if (mm[u]) { esum += e; cnt++; }     // mask values are 0/1
                }
            }
        }
    }

    // ---- deterministic block reduction ----
    float c = (float)cnt;
#pragma unroll
    for (int o = 16; o; o >>= 1) {
        esum += __shfl_down_sync(0xffffffffu, esum, o);
        c    += __shfl_down_sync(0xffffffffu, c, o);
    }
    if ((tid & 31) == 0) { w_es[tid >> 5] = esum; w_cn[tid >> 5] = c; }
    __syncthreads();
    if (tid == 0) {
        float es = 0.f, cc = 0.f;
#pragma unroll
        for (int k = 0; k < THREADS / 32; ++k) { es += w_es[k]; cc += w_cn[k]; }
        g_part[blockIdx.x] = cc - es;    // sum of (1 - exp(-d2/10)) over masked pairs
        __threadfence();
        const unsigned int old = atomicAdd(&g_done, 1u);
        s_last = (old == NBLK - 1);
    }
    __syncthreads();

    // ---- last block: fixed-order final reduction (deterministic) ----
    if (s_last) {
        float v = 0.f;
#pragma unroll
        for (int k = tid; k < NBLK; k += THREADS) v += g_part[k];
        qs[tid] = v;                      // reuse staged smem as scratch
        __syncthreads();
#pragma unroll
        for (int o = THREADS / 2; o; o >>= 1) {
            if (tid < o) qs[tid] += qs[tid + o];
            __syncthreads();
        }
        if (tid == 0) {
            out[0] = qs[0];
            g_done = 0;                   // reset for next launch / graph replay
        }
    }
}

extern "C" void kernel_launch(void* const* d_in, const int* in_sizes, int n_in,
                              void* d_out, int out_size) {
    const float* emb  = (const float*)d_in[0];   // embedding  [B,N,D] f32
    const float* crd  = (const float*)d_in[1];   // abs_coords [B,N,D] f32
    const int*   mask = (const int*)d_in[2];     // patch_mask [B,N,N] i32
    float* out = (float*)d_out;

    pair_kernel<<<NBLK, THREADS>>>(emb, crd, mask, out);
}

// round 8
// speedup vs baseline: 1.8302x; 1.3585x over previous
#include <cuda_runtime.h>

// Problem constants (fixed by the reference): B=8, N=2048, D=2
#define TB 8
#define TN 2048
#define BPB 111                     // blocks per batch (148 SMs * 6 blocks / 8 batches)
#define NBLK (TB * BPB)             // 888 = exactly one resident wave at 6 blocks/SM
#define THREADS 256
#define CIT 2                       // (TN/4)/THREADS column iterations (int4 granularity)
#define RSTRIDE (TN / 4)            // int4 per mask row (512)

// 2048 = 111*18 + 50  ->  sub < 50 handles 19 rows, else 18
#define EXTRA (TN - (TN / BPB) * BPB)   // 50

// Scratch (no allocation allowed in kernel_launch)
__device__ float g_part[NBLK];
__device__ unsigned int g_done;     // zero-init; last block resets it each run

__global__ __launch_bounds__(THREADS, 6) void pair_kernel(
    const float* __restrict__ emb, const float* __restrict__ crd,
    const int* __restrict__ mask, float* __restrict__ out) {
    __shared__ float qs[TN * 2];                 // scaled q[b], interleaved (x,y)
    __shared__ float w_es[THREADS / 32];
    __shared__ float w_cn[THREADS / 32];
    __shared__ int   s_last;

    const int tid = threadIdx.x;
    const int b   = blockIdx.x / BPB;
    const int sub = blockIdx.x % BPB;

    // ---- stage q[b] = (emb[b] + crd[b]) * sqrt(log2(e)/10) into smem ----
    const float S = 0.37982824f;                 // sqrt(log2(e)/10)
    const float4* e4 = (const float4*)(emb + (size_t)b * TN * 2);
    const float4* c4 = (const float4*)(crd + (size_t)b * TN * 2);
    float4* qs4 = (float4*)qs;
#pragma unroll
    for (int k = 0; k < (TN * 2 / 4) / THREADS; ++k) {       // 4 iters
        const float4 e = e4[tid + k * THREADS];
        const float4 c = c4[tid + k * THREADS];
        float4 q;
        q.x = (e.x + c.x) * S; q.y = (e.y + c.y) * S;
        q.z = (e.z + c.z) * S; q.w = (e.w + c.w) * S;
        qs4[tid + k * THREADS] = q;
    }
    __syncthreads();

    float esum = 0.f;
    int   cnt  = 0;

    const int4* mb = (const int4*)(mask + (size_t)b * TN * TN);
    const int nr = (sub < EXTRA) ? 19 : 18;      // rows r = sub + k*BPB

    int k = 0;
#pragma unroll 1
    for (; k + 2 <= nr; k += 2) {
        const int r0 = sub + k * BPB;
        const int r1 = r0 + BPB;
        // batch 4 independent int4 mask loads (2 rows x 2 col-iters)
        int4 m[2][CIT];
        m[0][0] = __ldcs(&mb[(size_t)r0 * RSTRIDE + tid]);
        m[0][1] = __ldcs(&mb[(size_t)r0 * RSTRIDE + tid + THREADS]);
        m[1][0] = __ldcs(&mb[(size_t)r1 * RSTRIDE + tid]);
        m[1][1] = __ldcs(&mb[(size_t)r1 * RSTRIDE + tid + THREADS]);

        const float q0x = qs[2 * r0], q0y = qs[2 * r0 + 1];
        const float q1x = qs[2 * r1], q1y = qs[2 * r1 + 1];

#pragma unroll
        for (int it = 0; it < CIT; ++it) {
            const int j4 = tid + it * THREADS;
            const float4 qa = qs4[2 * j4];       // cols 4j4, 4j4+1
            const float4 qb = qs4[2 * j4 + 1];   // cols 4j4+2, 4j4+3
            const float px[4] = {qa.x, qa.z, qb.x, qb.z};
            const float py[4] = {qa.y, qa.w, qb.y, qb.w};
            const int m0[4] = {m[0][it].x, m[0][it].y, m[0][it].z, m[0][it].w};
            const int m1[4] = {m[1][it].x, m[1][it].y, m[1][it].z, m[1][it].w};
#pragma unroll
            for (int u = 0; u < 4; ++u) {
                float dx = q0x - px[u], dy = q0y - py[u];
                float t = fmaf(dx, -dx, dy * -dy);   // -(dx^2+dy^2) in scaled space
                float e;
                asm("ex2.approx.ftz.f32 %0, %1;" : "=f"(e) : "f"(t));
                if (m0[u]) { esum += e; cnt++; }
                dx = q1x - px[u]; dy = q1y - py[u];
                t = fmaf(dx, -dx, dy * -dy);
                asm("ex2.approx.ftz.f32 %0, %1;" : "=f"(e) : "f"(t));
                if (m1[u]) { esum += e; cnt++; }
            }
        }
    }
    // tail row (only when nr is odd)
    if (k < nr) {
        const int r0 = sub + k * BPB;
        int4 ma = __ldcs(&mb[(size_t)r0 * RSTRIDE + tid]);
        int4 mc = __ldcs(&mb[(size_t)r0 * RSTRIDE + tid + THREADS]);
        const float q0x = qs[2 * r0], q0y = qs[2 * r0 + 1];
#pragma unroll
        for (int it = 0; it < CIT; ++it) {
            const int j4 = tid + it * THREADS;
            const float4 qa = qs4[2 * j4];
            const float4 qb = qs4[2 * j4 + 1];
            const float px[4] = {qa.x, qa.z, qb.x, qb.z};
            const float py[4] = {qa.y, qa.w, qb.y, qb.w};
            const int4 mm4 = (it == 0) ? ma : mc;
            const int mm[4] = {mm4.x, mm4.y, mm4.z, mm4.w};
#pragma unroll
            for (int u = 0; u < 4; ++u) {
                const float dx = q0x - px[u], dy = q0y - py[u];
                const float t = fmaf(dx, -dx, dy * -dy);
                float e;
                asm("ex2.approx.ftz.f32 %0, %1;" : "=f"(e) : "f"(t));
                if (mm[u]) { esum += e; cnt++; }
            }
        }
    }

    // ---- deterministic block reduction ----
    float c = (float)cnt;
#pragma unroll
    for (int o = 16; o; o >>= 1) {
        esum += __shfl_down_sync(0xffffffffu, esum, o);
        c    += __shfl_down_sync(0xffffffffu, c, o);
    }
    if ((tid & 31) == 0) { w_es[tid >> 5] = esum; w_cn[tid >> 5] = c; }
    __syncthreads();
    if (tid == 0) {
        float es = 0.f, cc = 0.f;
#pragma unroll
        for (int kk = 0; kk < THREADS / 32; ++kk) { es += w_es[kk]; cc += w_cn[kk]; }
        g_part[blockIdx.x] = cc - es;    // sum of (1 - exp(-d2/10)) over masked pairs
        __threadfence();
        const unsigned int old = atomicAdd(&g_done, 1u);
        s_last = (old == NBLK - 1);
    }
    __syncthreads();

    // ---- last block: fixed-order final reduction (deterministic) ----
    if (s_last) {
        float v = 0.f;
#pragma unroll
        for (int kk = tid; kk < NBLK; kk += THREADS) v += g_part[kk];
        qs[tid] = v;                      // reuse staged smem as scratch
        __syncthreads();
#pragma unroll
        for (int o = THREADS / 2; o; o >>= 1) {
            if (tid < o) qs[tid] += qs[tid + o];
            __syncthreads();
        }
        if (tid == 0) {
            out[0] = qs[0];
            g_done = 0;                   // reset for next launch / graph replay
        }
    }
}

extern "C" void kernel_launch(void* const* d_in, const int* in_sizes, int n_in,
                              void* d_out, int out_size) {
    const float* emb  = (const float*)d_in[0];   // embedding  [B,N,D] f32
    const float* crd  = (const float*)d_in[1];   // abs_coords [B,N,D] f32
    const int*   mask = (const int*)d_in[2];     // patch_mask [B,N,N] i32
    float* out = (float*)d_out;

    pair_kernel<<<NBLK, THREADS>>>(emb, crd, mask, out);
}